// round 12
// baseline (speedup 1.0000x reference)
#include <cuda_runtime.h>
#include <math.h>

#define BB 64
#define NN 4096
#define KS 16
#define DI 256
#define DO 256
#define HI 512
#define TT 3
#define LN_EPS 1e-5f
#define NCH 32   // n-chunks for the big attention pass (128 rows per block)
#define SCH 32   // chunks for streaming passes

// packed fp32x2 FMA (Blackwell FFMA2 — only reachable via PTX)
__device__ __forceinline__ void ffma2(float2& d, float2 a, float2 b) {
    asm("fma.rn.f32x2 %0, %1, %2, %0;"
        : "+l"(reinterpret_cast<unsigned long long&>(d))
        : "l"(reinterpret_cast<unsigned long long&>(a)),
          "l"(reinterpret_cast<unsigned long long&>(b)));
}

// cp.async helpers (LDGSTS)
__device__ __forceinline__ void cpasync16(void* smem, const void* gmem) {
    unsigned a = (unsigned)__cvta_generic_to_shared(smem);
    asm volatile("cp.async.cg.shared.global [%0], [%1], 16;" :: "r"(a), "l"(gmem));
}
__device__ __forceinline__ void cp_commit() {
    asm volatile("cp.async.commit_group;");
}
template <int N>
__device__ __forceinline__ void cp_wait() {
    asm volatile("cp.async.wait_group %0;" :: "n"(N));
}

// ---------------- device scratch (static, no allocations) ----------------
__device__ float g_spartA[SCH * BB];
__device__ float g_spartB[SCH * BB];
__device__ float g_mean[BB];
__device__ float g_rstd[BB];
__device__ float g_lnm[BB];        // LN1/LN2 stats (reused per stage)
__device__ float g_lnr[BB];
__device__ float g_xn[(size_t)BB * NN * DI];   // LN0(x), 268 MB
__device__ float g_slots[BB * KS * DO];
__device__ float g_qk[BB * KS * DI];     // PRE-scaled by 1/KS
__device__ float g_qkb[BB * KS];         // PRE-scaled by 1/KS
__device__ float g_upart[(size_t)NCH * BB * KS * DI];
__device__ float g_Spart[NCH * BB * KS];
__device__ float g_spre[BB * KS * DO];
// folded / transposed weights (per-iteration buffers, filled up front)
__device__ float g_Wqk[TT * DO * DI];
__device__ float g_wqb[TT * DI];
__device__ float g_wb[TT * DO];
__device__ float g_c0[TT];
__device__ float g_vWt[TT * DI * DO];
__device__ float g_m1Wt[TT * DO * HI];
__device__ float g_m2Wt[TT * HI * DO];

// ---------------- generic 32x32 tiled transpose -------------------------
__global__ void __launch_bounds__(256) k_tr(const float* __restrict__ src,
                                            float* __restrict__ dst, int R, int C) {
    __shared__ float tile[32][33];
    int z = blockIdx.z;
    const float* s = src + (size_t)z * R * C;
    float* d = dst + (size_t)z * R * C;
    int c0 = blockIdx.x * 32, r0 = blockIdx.y * 32;
    int x = threadIdx.x & 31, y = threadIdx.x >> 5;
    for (int yy = y; yy < 32; yy += 8)
        tile[yy][x] = s[(size_t)(r0 + yy) * C + c0 + x];
    __syncthreads();
    for (int yy = y; yy < 32; yy += 8)
        d[(size_t)(c0 + yy) * R + r0 + x] = tile[x][yy];
}

// ---------------- LN0 statistics ----------------------------------------
__global__ void __launch_bounds__(256) k_stats(const float* __restrict__ in) {
    int b = blockIdx.x, c = blockIdx.y, tid = threadIdx.x;
    const float4* p = (const float4*)(in + (size_t)b * NN * DI);
    const int per = (NN * DI / 4) / SCH;
    float s = 0.f, s2 = 0.f;
    for (int i = tid; i < per; i += 256) {
        float4 v = p[(size_t)c * per + i];
        s  += v.x + v.y + v.z + v.w;
        s2 += v.x * v.x + v.y * v.y + v.z * v.z + v.w * v.w;
    }
    __shared__ float r1[256], r2[256];
    r1[tid] = s; r2[tid] = s2; __syncthreads();
    for (int o = 128; o > 0; o >>= 1) {
        if (tid < o) { r1[tid] += r1[tid + o]; r2[tid] += r2[tid + o]; }
        __syncthreads();
    }
    if (tid == 0) { g_spartA[c * BB + b] = r1[0]; g_spartB[c * BB + b] = r2[0]; }
}

__global__ void k_fin() {
    int b = threadIdx.x;
    if (b >= BB) return;
    float s = 0.f, s2 = 0.f;
    for (int c = 0; c < SCH; c++) { s += g_spartA[c * BB + b]; s2 += g_spartB[c * BB + b]; }
    const float inv = 1.0f / (float)(NN * DI);
    float m = s * inv;
    float v = s2 * inv - m * m;
    g_mean[b] = m;
    g_rstd[b] = rsqrtf(v + LN_EPS);
}

// ---------------- x_hat = LN0(x) materialized once ----------------------
__global__ void __launch_bounds__(256) k_ln0(const float* __restrict__ in,
                                             const float* __restrict__ w,
                                             const float* __restrict__ bb) {
    int b = blockIdx.x, c = blockIdx.y, tid = threadIdx.x;
    const int per = (NN * DI / 4) / SCH;   // 8192 float4
    float mean = g_mean[b], rstd = g_rstd[b];
    const float4* xin = (const float4*)(in + (size_t)b * NN * DI) + (size_t)c * per;
    const float4* w4  = (const float4*)w  + (size_t)c * per;
    const float4* b4  = (const float4*)bb + (size_t)c * per;
    float4* xo = (float4*)(g_xn + (size_t)b * NN * DI) + (size_t)c * per;
    for (int i = tid; i < per; i += 256) {
        float4 v = xin[i], ww = w4[i], bv = b4[i], o;
        o.x = (v.x - mean) * rstd * ww.x + bv.x;
        o.y = (v.y - mean) * rstd * ww.y + bv.y;
        o.z = (v.z - mean) * rstd * ww.z + bv.z;
        o.w = (v.w - mean) * rstd * ww.w + bv.w;
        xo[i] = o;
    }
}

// ---------------- slots = mu + exp(logsigma) * slots_init ---------------
__global__ void k_sinit(const float* __restrict__ si, const float* __restrict__ mu,
                        const float* __restrict__ ls) {
    int i = blockIdx.x * 256 + threadIdx.x;
    int d = i & (DO - 1);
    g_slots[i] = mu[d] + expf(ls[d]) * si[i];
}

// ---------------- per-batch LN stats over [KS, DO]  (grid: BB) ----------
__global__ void __launch_bounds__(256) k_lnst(const float* __restrict__ src) {
    int b = blockIdx.x, tid = threadIdx.x;
    __shared__ float r1[256], r2[256];
    const float4* p = (const float4*)(src + (size_t)b * KS * DO);
    float s = 0.f, s2 = 0.f;
    for (int i = tid; i < KS * DO / 4; i += 256) {
        float4 v = p[i];
        s  += v.x + v.y + v.z + v.w;
        s2 += v.x * v.x + v.y * v.y + v.z * v.z + v.w * v.w;
    }
    r1[tid] = s; r2[tid] = s2; __syncthreads();
    for (int o = 128; o > 0; o >>= 1) {
        if (tid < o) { r1[tid] += r1[tid + o]; r2[tid] += r2[tid + o]; }
        __syncthreads();
    }
    if (tid == 0) {
        const float inv = 1.0f / (float)(KS * DO);
        float m = r1[0] * inv;
        g_lnm[b] = m;
        g_lnr[b] = rsqrtf(r2[0] * inv - m * m + LN_EPS);
    }
}

// ---------------- Wqk = qW^T @ kW  (grid: 64 x TT) ----------------------
__global__ void __launch_bounds__(256) k_wqk(const float* __restrict__ qW,
                                             const float* __restrict__ qb,
                                             const float* __restrict__ kW,
                                             const float* __restrict__ kb) {
    int d0 = blockIdx.x * 4, t = blockIdx.y, i = threadIdx.x;
    int wid = i >> 5, lane = i & 31;
    __shared__ float qcols[DO * 4];
    __shared__ float kb_s[DO], qb_s[DO];
    {
        float4 v = *(const float4*)(qW + (size_t)t * DO * DO + (size_t)i * DO + d0);
        qcols[i * 4 + 0] = v.x; qcols[i * 4 + 1] = v.y;
        qcols[i * 4 + 2] = v.z; qcols[i * 4 + 3] = v.w;
        kb_s[i] = kb[t * DO + i];
        qb_s[i] = qb[t * DO + i];
    }
    __syncthreads();
    const float* kWt = kW + (size_t)t * DO * DI;
    float acc0 = 0.f, acc1 = 0.f, acc2 = 0.f, acc3 = 0.f, accq = 0.f;
#pragma unroll 8
    for (int e = 0; e < DO; e++) {
        float kv = kWt[(size_t)e * DI + i];
        acc0 += qcols[e * 4 + 0] * kv;
        acc1 += qcols[e * 4 + 1] * kv;
        acc2 += qcols[e * 4 + 2] * kv;
        acc3 += qcols[e * 4 + 3] * kv;
        accq += qb_s[e] * kv;
    }
    float* Wq = g_Wqk + (size_t)t * DO * DI;
    Wq[(d0 + 0) * DI + i] = acc0;
    Wq[(d0 + 1) * DI + i] = acc1;
    Wq[(d0 + 2) * DI + i] = acc2;
    Wq[(d0 + 3) * DI + i] = acc3;
    if (blockIdx.x == 0) g_wqb[t * DI + i] = accq;
    if (wid < 4) {
        float s = 0.f;
        for (int e = lane; e < DO; e += 32) s += qcols[e * 4 + wid] * kb_s[e];
#pragma unroll
        for (int o = 16; o > 0; o >>= 1) s += __shfl_xor_sync(0xffffffffu, s, o);
        if (lane == 0) g_wb[t * DO + d0 + wid] = s;
    }
    if (blockIdx.x == 0 && wid == 4) {
        float s = 0.f;
        for (int e = lane; e < DO; e += 32) s += qb_s[e] * kb_s[e];
#pragma unroll
        for (int o = 16; o > 0; o >>= 1) s += __shfl_xor_sync(0xffffffffu, s, o);
        if (lane == 0) g_c0[t] = s;
    }
}

// ---------------- qk = LN1(slots) @ Wqk + wqb  (grid: 8 kh x 8 bg) ------
// Batch-grouped: 2 slots x 8 batches per block; Wqk read once per block.
__global__ void __launch_bounds__(256) k_qk(const float* __restrict__ ln1w,
                                            const float* __restrict__ ln1b, int t) {
    int kh = blockIdx.x, bg = blockIdx.y, tid = threadIdx.x;
    int wid = tid >> 5, lane = tid & 31;
    int b0 = bg * 8, k0 = kh * 2;
    __shared__ float ss[16 * DO];   // row = bl*2 + k (bl = local batch)
    __shared__ float wbs[DO];
    for (int idx = tid; idx < 16 * DO; idx += 256) {
        int row = idx >> 8, d = idx & 255;
        int b = b0 + (row >> 1), sl = k0 + (row & 1);
        float v = g_slots[(size_t)b * KS * DO + sl * DO + d];
        ss[idx] = (v - g_lnm[b]) * g_lnr[b] * ln1w[sl * DO + d] + ln1b[sl * DO + d];
    }
    wbs[tid] = g_wb[t * DO + tid];
    __syncthreads();

    const float isc = 1.0f / (float)KS;
    const float* Wq = g_Wqk + (size_t)t * DO * DI;
    float2 acc[8];
#pragma unroll
    for (int p = 0; p < 8; p++) acc[p] = make_float2(0.f, 0.f);
#pragma unroll 8
    for (int d = 0; d < DO; d++) {
        float wv = Wq[d * DI + tid];
        float2 w2 = make_float2(wv, wv);
#pragma unroll
        for (int p = 0; p < 8; p++)
            ffma2(acc[p], make_float2(ss[(2 * p) * DO + d], ss[(2 * p + 1) * DO + d]), w2);
    }
    float wqbv = g_wqb[t * DI + tid];
#pragma unroll
    for (int p = 0; p < 8; p++) {
        int b = b0 + p;
        g_qk[(size_t)b * KS * DI + (k0 + 0) * DI + tid] = (acc[p].x + wqbv) * isc;
        g_qk[(size_t)b * KS * DI + (k0 + 1) * DI + tid] = (acc[p].y + wqbv) * isc;
    }
    // qkb: each warp handles rows 2wid, 2wid+1
#pragma unroll
    for (int r = wid * 2; r < wid * 2 + 2; r++) {
        float sb = 0.f;
        for (int d = lane; d < DO; d += 32) sb += ss[r * DO + d] * wbs[d];
#pragma unroll
        for (int o = 16; o > 0; o >>= 1) sb += __shfl_xor_sync(0xffffffffu, sb, o);
        if (lane == 0) {
            int b = b0 + (r >> 1), sl = k0 + (r & 1);
            g_qkb[b * KS + sl] = (sb + g_c0[t]) * isc;
        }
    }
}

// ---------------- big fused attention pass  (grid: BB x NCH) ------------
// LDS.128 loads, fused parallel softmax, occ 4, cp.async double buffering.
__global__ void __launch_bounds__(256, 4) k_attn() {
    int b = blockIdx.x, ch = blockIdx.y, tid = threadIdx.x;
    int kk = tid & 15, dg = tid >> 4;
    int wid = tid >> 5, lane = tid & 31;

    __shared__ float4 xs[2][16 * 64];    // double-buffered tiles, 32 KB (no pad: reads broadcast)
    __shared__ float  attn[KS][17];
    __shared__ float  red[8][16 * 17];
    __shared__ float  qkb_s[KS];

    // qk segment for (kk, dg): 16 floats as 8 float2 (already /KS scaled)
    const float2* qp = (const float2*)(g_qk + ((size_t)b * KS + kk) * DI + dg * 16);
    float2 q[8];
#pragma unroll
    for (int j = 0; j < 8; j++) q[j] = qp[j];
    if (tid < KS) qkb_s[tid] = g_qkb[b * KS + tid];

    float2 u[8];
#pragma unroll
    for (int j = 0; j < 8; j++) u[j] = make_float2(0.f, 0.f);
    float Sa = 0.f;

    const float4* xnb = (const float4*)(g_xn + ((size_t)b * NN + (size_t)ch * 128) * DI);

    // prefetch tile 0 (linear layout, stride 64 float4)
#pragma unroll
    for (int k = 0; k < 4; k++) {
        int i = tid + k * 256;
        cpasync16(&xs[0][i], &xnb[i]);
    }
    cp_commit();

    for (int g = 0; g < 8; g++) {
        const float4* buf = xs[g & 1];
        if (g < 7) {
            float4* nb = xs[(g + 1) & 1];
            const float4* src = xnb + (size_t)(g + 1) * 1024;
#pragma unroll
            for (int k = 0; k < 4; k++) {
                int i = tid + k * 256;
                cpasync16(&nb[i], &src[i]);
            }
            cp_commit();
            cp_wait<1>();
        } else {
            cp_wait<0>();
        }
        __syncthreads();

        // phase1: float4 partial dots; immediate shfl-fold + store (no p[] array)
#pragma unroll
        for (int n = 0; n < 16; n++) {
            const float4* xr = &buf[n * 64 + dg * 4];
            float2 acc = make_float2(0.f, 0.f);
#pragma unroll
            for (int j = 0; j < 4; j++) {
                float4 xv = xr[j];
                ffma2(acc, q[2 * j],     make_float2(xv.x, xv.y));
                ffma2(acc, q[2 * j + 1], make_float2(xv.z, xv.w));
            }
            float p = acc.x + acc.y;
            p += __shfl_xor_sync(0xffffffffu, p, 16);   // fold dg pair
            if (lane < 16) red[wid][lane * 17 + n] = p;
        }
        __syncthreads();

        // fused dist-assembly + softmax: thread (rkk = tid&15, rn = tid>>4).
        // All 16 slots of one n sit in a 16-lane half-warp -> shfl reductions.
        {
            int rkk = tid & 15, rn = tid >> 4;
            float s = qkb_s[rkk];
#pragma unroll
            for (int w = 0; w < 8; w++) s += red[w][rkk * 17 + rn];
            float mx = s;
#pragma unroll
            for (int o = 1; o < 16; o <<= 1)
                mx = fmaxf(mx, __shfl_xor_sync(0xffffffffu, mx, o));
            float e = __expf(s - mx);
            float sm = e;
#pragma unroll
            for (int o = 1; o < 16; o <<= 1)
                sm += __shfl_xor_sync(0xffffffffu, sm, o);
            attn[rkk][rn] = e * (1.0f / sm);
        }
        __syncthreads();

        if (tid < 16) {
#pragma unroll
            for (int n = 0; n < 16; n++) Sa += attn[tid][n];
        }

        // phase2: float4 x loads (broadcast), packed u accumulation
#pragma unroll
        for (int n = 0; n < 16; n++) {
            float w = attn[kk][n];
            float2 w2 = make_float2(w, w);
            const float4* xr = &buf[n * 64 + dg * 4];
#pragma unroll
            for (int j = 0; j < 4; j++) {
                float4 xv = xr[j];
                ffma2(u[2 * j],     w2, make_float2(xv.x, xv.y));
                ffma2(u[2 * j + 1], w2, make_float2(xv.z, xv.w));
            }
        }
        __syncthreads();   // all reads of buf done -> safe to prefetch into it
    }

    float4* up = (float4*)(g_upart + (((size_t)ch * BB + b) * KS + kk) * DI + dg * 16);
    up[0] = make_float4(u[0].x, u[0].y, u[1].x, u[1].y);
    up[1] = make_float4(u[2].x, u[2].y, u[3].x, u[3].y);
    up[2] = make_float4(u[4].x, u[4].y, u[5].x, u[5].y);
    up[3] = make_float4(u[6].x, u[6].y, u[7].x, u[7].y);
    if (tid < 16) g_Spart[(ch * BB + b) * KS + tid] = Sa;
}

// ---------------- reduce partials, V proj  (grid: BB x 4) ---------------
// 4 slots per block; one thread per (slot, float4-pos) in the reduce.
__global__ void __launch_bounds__(256) k_vproj(const float* __restrict__ vb, int t) {
    int b = blockIdx.x, kh = blockIdx.y, tid = threadIdx.x;
    __shared__ float wxs[4 * DI];
    __shared__ float wss[4], ivs[4];
    if (tid < 4) {
        float S = 0.f;
#pragma unroll 8
        for (int c = 0; c < NCH; c++) S += g_Spart[(c * BB + b) * KS + kh * 4 + tid];
        float iv = 1.0f / (S + 1e-7f);
        ivs[tid] = iv; wss[tid] = S * iv;
    }
    __syncthreads();
    {
        int k = tid >> 6, pos = tid & 63;   // 4 slots x 64 float4 = 256 threads
        const float4* src = (const float4*)g_upart +
            (((size_t)b * KS) + kh * 4 + k) * (DI / 4) + pos;
        float4 s = make_float4(0.f, 0.f, 0.f, 0.f);
#pragma unroll 8
        for (int c = 0; c < NCH; c++) {
            float4 v = src[(size_t)c * (BB * KS * DI / 4)];
            s.x += v.x; s.y += v.y; s.z += v.z; s.w += v.w;
        }
        float iv = ivs[k];
        s.x *= iv; s.y *= iv; s.z *= iv; s.w *= iv;
        ((float4*)wxs)[tid] = s;
    }
    __syncthreads();
    const float* vt = g_vWt + (size_t)t * DI * DO;
    float acc0 = 0.f, acc1 = 0.f, acc2 = 0.f, acc3 = 0.f;
#pragma unroll 8
    for (int d = 0; d < DI; d++) {
        float wv = vt[(size_t)d * DO + tid];
        acc0 += wxs[0 * DI + d] * wv;
        acc1 += wxs[1 * DI + d] * wv;
        acc2 += wxs[2 * DI + d] * wv;
        acc3 += wxs[3 * DI + d] * wv;
    }
    float vbv = vb[t * DO + tid];
    g_spre[b * KS * DO + (kh * 4 + 0) * DO + tid] = acc0 + vbv * wss[0];
    g_spre[b * KS * DO + (kh * 4 + 1) * DO + tid] = acc1 + vbv * wss[1];
    g_spre[b * KS * DO + (kh * 4 + 2) * DO + tid] = acc2 + vbv * wss[2];
    g_spre[b * KS * DO + (kh * 4 + 3) * DO + tid] = acc3 + vbv * wss[3];
}

// ---------------- LN2 + MLP + residual  (grid: 8 kq x 16 bg) ------------
// Batch-grouped: 2 slots x 4 batches = 8 rows; weights read once per block;
// row-paired FFMA2 halves FMA instruction count.
__global__ void __launch_bounds__(256) k_mlp(const float* __restrict__ ln2w,
                                             const float* __restrict__ ln2b,
                                             const float* __restrict__ m1b,
                                             const float* __restrict__ m2b,
                                             int t, float* __restrict__ out) {
    int kq = blockIdx.x, bg = blockIdx.y, tid = threadIdx.x;
    int b0 = bg * 4, k0 = kq * 2;
    __shared__ float h0[8 * DO];    // 8 KB, row = bl*2 + k
    __shared__ float hh[8 * HI];    // 16 KB
    for (int idx = tid; idx < 8 * DO; idx += 256) {
        int row = idx >> 8, d = idx & 255;
        int b = b0 + (row >> 1), sl = k0 + (row & 1);
        float v = g_spre[(size_t)b * KS * DO + sl * DO + d];
        h0[idx] = (v - g_lnm[b]) * g_lnr[b] * ln2w[sl * DO + d] + ln2b[sl * DO + d];
    }
    __syncthreads();

    const float* w1 = g_m1Wt + (size_t)t * DO * HI;
    float2 a0[4], a1[4];
#pragma unroll
    for (int p = 0; p < 4; p++) { a0[p] = make_float2(0.f, 0.f); a1[p] = make_float2(0.f, 0.f); }
#pragma unroll 8
    for (int d = 0; d < DO; d++) {
        float wA = w1[(size_t)d * HI + tid];
        float wB = w1[(size_t)d * HI + tid + 256];
        float2 wa = make_float2(wA, wA), wb2 = make_float2(wB, wB);
#pragma unroll
        for (int p = 0; p < 4; p++) {
            float2 hp = make_float2(h0[(2 * p) * DO + d], h0[(2 * p + 1) * DO + d]);
            ffma2(a0[p], hp, wa);
            ffma2(a1[p], hp, wb2);
        }
    }
    float bA = m1b[t * HI + tid], bB = m1b[t * HI + tid + 256];
#pragma unroll
    for (int p = 0; p < 4; p++) {
        hh[(2 * p) * HI + tid]           = fmaxf(a0[p].x + bA, 0.f);
        hh[(2 * p + 1) * HI + tid]       = fmaxf(a0[p].y + bA, 0.f);
        hh[(2 * p) * HI + tid + 256]     = fmaxf(a1[p].x + bB, 0.f);
        hh[(2 * p + 1) * HI + tid + 256] = fmaxf(a1[p].y + bB, 0.f);
    }
    __syncthreads();

    const float* w2 = g_m2Wt + (size_t)t * HI * DO;
    float2 a2[4];
#pragma unroll
    for (int p = 0; p < 4; p++) a2[p] = make_float2(0.f, 0.f);
#pragma unroll 8
    for (int h = 0; h < HI; h++) {
        float wv = w2[(size_t)h * DO + tid];
        float2 w2v = make_float2(wv, wv);
#pragma unroll
        for (int p = 0; p < 4; p++)
            ffma2(a2[p], make_float2(hh[(2 * p) * HI + h], hh[(2 * p + 1) * HI + h]), w2v);
    }
    float b2 = m2b[t * DO + tid];
#pragma unroll
    for (int p = 0; p < 4; p++) {
        int b = b0 + p;
        size_t gi0 = (size_t)b * KS * DO + (k0 + 0) * DO + tid;
        size_t gi1 = (size_t)b * KS * DO + (k0 + 1) * DO + tid;
        float v0 = g_spre[gi0] + a2[p].x + b2;
        float v1 = g_spre[gi1] + a2[p].y + b2;
        g_slots[gi0] = v0;
        g_slots[gi1] = v1;
        if (out) { out[gi0] = v0; out[gi1] = v1; }
    }
}

// ---------------- host launcher -----------------------------------------
extern "C" void kernel_launch(void* const* d_in, const int* in_sizes, int n_in,
                              void* d_out, int out_size) {
    const float* inputs     = (const float*)d_in[0];
    const float* slots_init = (const float*)d_in[1];
    const float* mu         = (const float*)d_in[2];
    const float* logsigma   = (const float*)d_in[3];
    const float* ln0w       = (const float*)d_in[4];
    const float* ln0b       = (const float*)d_in[5];
    const float* ln1w       = (const float*)d_in[6];
    const float* ln1b       = (const float*)d_in[7];
    const float* ln2w       = (const float*)d_in[8];
    const float* ln2b       = (const float*)d_in[9];
    const float* qW         = (const float*)d_in[10];
    const float* qb         = (const float*)d_in[11];
    const float* kW         = (const float*)d_in[12];
    const float* kb         = (const float*)d_in[13];
    const float* vW         = (const float*)d_in[14];
    const float* vb         = (const float*)d_in[15];
    const float* m1W        = (const float*)d_in[16];
    const float* m1b        = (const float*)d_in[17];
    const float* m2W        = (const float*)d_in[18];
    const float* m2b        = (const float*)d_in[19];
    float* out = (float*)d_out;

    float* vWt;   cudaGetSymbolAddress((void**)&vWt,   g_vWt);
    float* m1Wt;  cudaGetSymbolAddress((void**)&m1Wt,  g_m1Wt);
    float* m2Wt;  cudaGetSymbolAddress((void**)&m2Wt,  g_m2Wt);
    float* slotsp; cudaGetSymbolAddress((void**)&slotsp, g_slots);
    float* sprep;  cudaGetSymbolAddress((void**)&sprep,  g_spre);

    k_tr<<<dim3(DI / 32, DO / 32, TT), 256>>>(vW, vWt, DO, DI);
    k_tr<<<dim3(DO / 32, HI / 32, TT), 256>>>(m1W, m1Wt, HI, DO);
    k_tr<<<dim3(HI / 32, DO / 32, TT), 256>>>(m2W, m2Wt, DO, HI);

    k_wqk<<<dim3(64, TT), 256>>>(qW, qb, kW, kb);   // all iterations up front
    k_stats<<<dim3(BB, SCH), 256>>>(inputs);
    k_fin<<<1, BB>>>();
    k_ln0<<<dim3(BB, SCH), 256>>>(inputs, ln0w, ln0b);
    k_sinit<<<(BB * KS * DO) / 256, 256>>>(slots_init, mu, logsigma);

    for (int t = 0; t < TT; t++) {
        k_lnst<<<BB, 256>>>(slotsp);
        k_qk<<<dim3(8, 8), 256>>>(ln1w, ln1b, t);
        k_attn<<<dim3(BB, NCH), 256>>>();
        k_vproj<<<dim3(BB, 4), 256>>>(vb, t);
        k_lnst<<<BB, 256>>>(sprep);
        k_mlp<<<dim3(8, 16), 256>>>(ln2w, ln2b, m1b, m2b, t,
                                    (t == TT - 1) ? out : (float*)nullptr);
    }
}

// round 13
// speedup vs baseline: 1.0181x; 1.0181x over previous
#include <cuda_runtime.h>
#include <math.h>

#define BB 64
#define NN 4096
#define KS 16
#define DI 256
#define DO 256
#define HI 512
#define TT 3
#define LN_EPS 1e-5f
#define NCH 32   // n-chunks for the big attention pass (128 rows per block)
#define SCH 32   // chunks for streaming passes

// packed fp32x2 FMA (Blackwell FFMA2 — only reachable via PTX)
__device__ __forceinline__ void ffma2(float2& d, float2 a, float2 b) {
    asm("fma.rn.f32x2 %0, %1, %2, %0;"
        : "+l"(reinterpret_cast<unsigned long long&>(d))
        : "l"(reinterpret_cast<unsigned long long&>(a)),
          "l"(reinterpret_cast<unsigned long long&>(b)));
}

// cp.async helpers (LDGSTS)
__device__ __forceinline__ void cpasync16(void* smem, const void* gmem) {
    unsigned a = (unsigned)__cvta_generic_to_shared(smem);
    asm volatile("cp.async.cg.shared.global [%0], [%1], 16;" :: "r"(a), "l"(gmem));
}
__device__ __forceinline__ void cp_commit() {
    asm volatile("cp.async.commit_group;");
}
template <int N>
__device__ __forceinline__ void cp_wait() {
    asm volatile("cp.async.wait_group %0;" :: "n"(N));
}

// ---------------- device scratch (static, no allocations) ----------------
__device__ float g_spartA[SCH * BB];
__device__ float g_spartB[SCH * BB];
__device__ float g_mean[BB];
__device__ float g_rstd[BB];
__device__ float g_lnm[BB];            // slots stats from k_sinit (t=0 path)
__device__ float g_lnr[BB];
__device__ float g_lnpA[BB * 8];       // slots partial stats from k_mlp (t>0)
__device__ float g_lnpB[BB * 8];
__device__ float g_lnqA[BB * 4];       // spre partial stats from k_vproj
__device__ float g_lnqB[BB * 4];
__device__ float g_xn[(size_t)BB * NN * DI];   // LN0(x), 268 MB
__device__ float g_slots[BB * KS * DO];
__device__ float g_qk[BB * KS * DI];     // PRE-scaled by 1/KS
__device__ float g_qkb[BB * KS];         // PRE-scaled by 1/KS
__device__ float g_upart[(size_t)NCH * BB * KS * DI];
__device__ float g_Spart[NCH * BB * KS];
__device__ float g_spre[BB * KS * DO];
// folded / transposed weights (per-iteration buffers, filled up front)
__device__ float g_Wqk[TT * DO * DI];
__device__ float g_wqb[TT * DI];
__device__ float g_wb[TT * DO];
__device__ float g_c0[TT];
__device__ float g_vWt[TT * DI * DO];
__device__ float g_m1Wt[TT * DO * HI];
__device__ float g_m2Wt[TT * HI * DO];

// ---------------- generic 32x32 tiled transpose -------------------------
__global__ void __launch_bounds__(256) k_tr(const float* __restrict__ src,
                                            float* __restrict__ dst, int R, int C) {
    __shared__ float tile[32][33];
    int z = blockIdx.z;
    const float* s = src + (size_t)z * R * C;
    float* d = dst + (size_t)z * R * C;
    int c0 = blockIdx.x * 32, r0 = blockIdx.y * 32;
    int x = threadIdx.x & 31, y = threadIdx.x >> 5;
    for (int yy = y; yy < 32; yy += 8)
        tile[yy][x] = s[(size_t)(r0 + yy) * C + c0 + x];
    __syncthreads();
    for (int yy = y; yy < 32; yy += 8)
        d[(size_t)(c0 + yy) * R + r0 + x] = tile[x][yy];
}

// ---------------- LN0 statistics ----------------------------------------
__global__ void __launch_bounds__(256) k_stats(const float* __restrict__ in) {
    int b = blockIdx.x, c = blockIdx.y, tid = threadIdx.x;
    const float4* p = (const float4*)(in + (size_t)b * NN * DI);
    const int per = (NN * DI / 4) / SCH;
    float s = 0.f, s2 = 0.f;
    for (int i = tid; i < per; i += 256) {
        float4 v = p[(size_t)c * per + i];
        s  += v.x + v.y + v.z + v.w;
        s2 += v.x * v.x + v.y * v.y + v.z * v.z + v.w * v.w;
    }
    __shared__ float r1[256], r2[256];
    r1[tid] = s; r2[tid] = s2; __syncthreads();
    for (int o = 128; o > 0; o >>= 1) {
        if (tid < o) { r1[tid] += r1[tid + o]; r2[tid] += r2[tid + o]; }
        __syncthreads();
    }
    if (tid == 0) { g_spartA[c * BB + b] = r1[0]; g_spartB[c * BB + b] = r2[0]; }
}

__global__ void k_fin() {
    int b = threadIdx.x;
    if (b >= BB) return;
    float s = 0.f, s2 = 0.f;
    for (int c = 0; c < SCH; c++) { s += g_spartA[c * BB + b]; s2 += g_spartB[c * BB + b]; }
    const float inv = 1.0f / (float)(NN * DI);
    float m = s * inv;
    float v = s2 * inv - m * m;
    g_mean[b] = m;
    g_rstd[b] = rsqrtf(v + LN_EPS);
}

// ---------------- x_hat = LN0(x) materialized once ----------------------
__global__ void __launch_bounds__(256) k_ln0(const float* __restrict__ in,
                                             const float* __restrict__ w,
                                             const float* __restrict__ bb) {
    int b = blockIdx.x, c = blockIdx.y, tid = threadIdx.x;
    const int per = (NN * DI / 4) / SCH;   // 8192 float4
    float mean = g_mean[b], rstd = g_rstd[b];
    const float4* xin = (const float4*)(in + (size_t)b * NN * DI) + (size_t)c * per;
    const float4* w4  = (const float4*)w  + (size_t)c * per;
    const float4* b4  = (const float4*)bb + (size_t)c * per;
    float4* xo = (float4*)(g_xn + (size_t)b * NN * DI) + (size_t)c * per;
    for (int i = tid; i < per; i += 256) {
        float4 v = xin[i], ww = w4[i], bv = b4[i], o;
        o.x = (v.x - mean) * rstd * ww.x + bv.x;
        o.y = (v.y - mean) * rstd * ww.y + bv.y;
        o.z = (v.z - mean) * rstd * ww.z + bv.z;
        o.w = (v.w - mean) * rstd * ww.w + bv.w;
        xo[i] = o;
    }
}

// ---------------- slots = mu + exp(logsigma)*slots_init + LN stats ------
// One block per batch: also emits g_lnm/g_lnr for iteration-0 LN1.
__global__ void __launch_bounds__(256) k_sinit(const float* __restrict__ si,
                                               const float* __restrict__ mu,
                                               const float* __restrict__ ls) {
    int b = blockIdx.x, tid = threadIdx.x;
    const float4* sp = (const float4*)(si + (size_t)b * KS * DO);
    float4* op = (float4*)(g_slots + (size_t)b * KS * DO);
    float s = 0.f, s2 = 0.f;
#pragma unroll
    for (int k = 0; k < 4; k++) {
        int i = tid + k * 256;          // 1024 float4 per batch
        int d = (i * 4) & (DO - 1);
        float4 v = sp[i], o;
        o.x = mu[d + 0] + expf(ls[d + 0]) * v.x;
        o.y = mu[d + 1] + expf(ls[d + 1]) * v.y;
        o.z = mu[d + 2] + expf(ls[d + 2]) * v.z;
        o.w = mu[d + 3] + expf(ls[d + 3]) * v.w;
        op[i] = o;
        s  += o.x + o.y + o.z + o.w;
        s2 += o.x * o.x + o.y * o.y + o.z * o.z + o.w * o.w;
    }
    __shared__ float r1[256], r2[256];
    r1[tid] = s; r2[tid] = s2; __syncthreads();
    for (int o = 128; o > 0; o >>= 1) {
        if (tid < o) { r1[tid] += r1[tid + o]; r2[tid] += r2[tid + o]; }
        __syncthreads();
    }
    if (tid == 0) {
        const float inv = 1.0f / (float)(KS * DO);
        float m = r1[0] * inv;
        g_lnm[b] = m;
        g_lnr[b] = rsqrtf(r2[0] * inv - m * m + LN_EPS);
    }
}

// ---------------- Wqk = qW^T @ kW  (grid: 64 x TT) ----------------------
__global__ void __launch_bounds__(256) k_wqk(const float* __restrict__ qW,
                                             const float* __restrict__ qb,
                                             const float* __restrict__ kW,
                                             const float* __restrict__ kb) {
    int d0 = blockIdx.x * 4, t = blockIdx.y, i = threadIdx.x;
    int wid = i >> 5, lane = i & 31;
    __shared__ float qcols[DO * 4];
    __shared__ float kb_s[DO], qb_s[DO];
    {
        float4 v = *(const float4*)(qW + (size_t)t * DO * DO + (size_t)i * DO + d0);
        qcols[i * 4 + 0] = v.x; qcols[i * 4 + 1] = v.y;
        qcols[i * 4 + 2] = v.z; qcols[i * 4 + 3] = v.w;
        kb_s[i] = kb[t * DO + i];
        qb_s[i] = qb[t * DO + i];
    }
    __syncthreads();
    const float* kWt = kW + (size_t)t * DO * DI;
    float acc0 = 0.f, acc1 = 0.f, acc2 = 0.f, acc3 = 0.f, accq = 0.f;
#pragma unroll 8
    for (int e = 0; e < DO; e++) {
        float kv = kWt[(size_t)e * DI + i];
        acc0 += qcols[e * 4 + 0] * kv;
        acc1 += qcols[e * 4 + 1] * kv;
        acc2 += qcols[e * 4 + 2] * kv;
        acc3 += qcols[e * 4 + 3] * kv;
        accq += qb_s[e] * kv;
    }
    float* Wq = g_Wqk + (size_t)t * DO * DI;
    Wq[(d0 + 0) * DI + i] = acc0;
    Wq[(d0 + 1) * DI + i] = acc1;
    Wq[(d0 + 2) * DI + i] = acc2;
    Wq[(d0 + 3) * DI + i] = acc3;
    if (blockIdx.x == 0) g_wqb[t * DI + i] = accq;
    if (wid < 4) {
        float s = 0.f;
        for (int e = lane; e < DO; e += 32) s += qcols[e * 4 + wid] * kb_s[e];
#pragma unroll
        for (int o = 16; o > 0; o >>= 1) s += __shfl_xor_sync(0xffffffffu, s, o);
        if (lane == 0) g_wb[t * DO + d0 + wid] = s;
    }
    if (blockIdx.x == 0 && wid == 4) {
        float s = 0.f;
        for (int e = lane; e < DO; e += 32) s += qb_s[e] * kb_s[e];
#pragma unroll
        for (int o = 16; o > 0; o >>= 1) s += __shfl_xor_sync(0xffffffffu, s, o);
        if (lane == 0) g_c0[t] = s;
    }
}

// ---------------- qk = LN1(slots) @ Wqk + wqb  (grid: 8 kh x 8 bg) ------
// Batch-grouped: 2 slots x 8 batches; finalizes LN1 stats from partials.
__global__ void __launch_bounds__(256) k_qk(const float* __restrict__ ln1w,
                                            const float* __restrict__ ln1b,
                                            int t, int first) {
    int kh = blockIdx.x, bg = blockIdx.y, tid = threadIdx.x;
    int wid = tid >> 5, lane = tid & 31;
    int b0 = bg * 8, k0 = kh * 2;
    __shared__ float ss[16 * DO];   // row = bl*2 + k (bl = local batch)
    __shared__ float wbs[DO];
    __shared__ float bm[8], br[8];
    if (tid < 8) {
        int b = b0 + tid;
        float m, rs;
        if (first) { m = g_lnm[b]; rs = g_lnr[b]; }
        else {
            float s = 0.f, s2 = 0.f;
#pragma unroll
            for (int j = 0; j < 8; j++) { s += g_lnpA[b * 8 + j]; s2 += g_lnpB[b * 8 + j]; }
            const float inv = 1.0f / (float)(KS * DO);
            m = s * inv;
            rs = rsqrtf(s2 * inv - m * m + LN_EPS);
        }
        bm[tid] = m; br[tid] = rs;
    }
    wbs[tid] = g_wb[t * DO + tid];
    __syncthreads();
    for (int idx = tid; idx < 16 * DO; idx += 256) {
        int row = idx >> 8, d = idx & 255;
        int bl = row >> 1, b = b0 + bl, sl = k0 + (row & 1);
        float v = g_slots[(size_t)b * KS * DO + sl * DO + d];
        ss[idx] = (v - bm[bl]) * br[bl] * ln1w[sl * DO + d] + ln1b[sl * DO + d];
    }
    __syncthreads();

    const float isc = 1.0f / (float)KS;
    const float* Wq = g_Wqk + (size_t)t * DO * DI;
    float2 acc[8];
#pragma unroll
    for (int p = 0; p < 8; p++) acc[p] = make_float2(0.f, 0.f);
#pragma unroll 8
    for (int d = 0; d < DO; d++) {
        float wv = Wq[d * DI + tid];
        float2 w2 = make_float2(wv, wv);
#pragma unroll
        for (int p = 0; p < 8; p++)
            ffma2(acc[p], make_float2(ss[(2 * p) * DO + d], ss[(2 * p + 1) * DO + d]), w2);
    }
    float wqbv = g_wqb[t * DI + tid];
#pragma unroll
    for (int p = 0; p < 8; p++) {
        int b = b0 + p;
        g_qk[(size_t)b * KS * DI + (k0 + 0) * DI + tid] = (acc[p].x + wqbv) * isc;
        g_qk[(size_t)b * KS * DI + (k0 + 1) * DI + tid] = (acc[p].y + wqbv) * isc;
    }
    // qkb: each warp handles rows 2wid, 2wid+1
#pragma unroll
    for (int r = wid * 2; r < wid * 2 + 2; r++) {
        float sb = 0.f;
        for (int d = lane; d < DO; d += 32) sb += ss[r * DO + d] * wbs[d];
#pragma unroll
        for (int o = 16; o > 0; o >>= 1) sb += __shfl_xor_sync(0xffffffffu, sb, o);
        if (lane == 0) {
            int b = b0 + (r >> 1), sl = k0 + (r & 1);
            g_qkb[b * KS + sl] = (sb + g_c0[t]) * isc;
        }
    }
}

// ---------------- big fused attention pass  (grid: BB x NCH) ------------
// LDS.128 loads, fused parallel softmax, occ 3 (regs=80; occ4 spills — R12),
// cp.async double buffering.
__global__ void __launch_bounds__(256, 3) k_attn() {
    int b = blockIdx.x, ch = blockIdx.y, tid = threadIdx.x;
    int kk = tid & 15, dg = tid >> 4;
    int wid = tid >> 5, lane = tid & 31;

    __shared__ float4 xs[2][16 * 64];    // double-buffered tiles, 32 KB
    __shared__ float  attn[KS][17];
    __shared__ float  red[8][16 * 17];
    __shared__ float  qkb_s[KS];

    // qk segment for (kk, dg): 16 floats as 8 float2 (already /KS scaled)
    const float2* qp = (const float2*)(g_qk + ((size_t)b * KS + kk) * DI + dg * 16);
    float2 q[8];
#pragma unroll
    for (int j = 0; j < 8; j++) q[j] = qp[j];
    if (tid < KS) qkb_s[tid] = g_qkb[b * KS + tid];

    float2 u[8];
#pragma unroll
    for (int j = 0; j < 8; j++) u[j] = make_float2(0.f, 0.f);
    float Sa = 0.f;

    const float4* xnb = (const float4*)(g_xn + ((size_t)b * NN + (size_t)ch * 128) * DI);

    // prefetch tile 0 (linear layout, stride 64 float4)
#pragma unroll
    for (int k = 0; k < 4; k++) {
        int i = tid + k * 256;
        cpasync16(&xs[0][i], &xnb[i]);
    }
    cp_commit();

    for (int g = 0; g < 8; g++) {
        const float4* buf = xs[g & 1];
        if (g < 7) {
            float4* nb = xs[(g + 1) & 1];
            const float4* src = xnb + (size_t)(g + 1) * 1024;
#pragma unroll
            for (int k = 0; k < 4; k++) {
                int i = tid + k * 256;
                cpasync16(&nb[i], &src[i]);
            }
            cp_commit();
            cp_wait<1>();
        } else {
            cp_wait<0>();
        }
        __syncthreads();

        // phase1: float4 partial dots; immediate shfl-fold + store
#pragma unroll
        for (int n = 0; n < 16; n++) {
            const float4* xr = &buf[n * 64 + dg * 4];
            float2 acc = make_float2(0.f, 0.f);
#pragma unroll
            for (int j = 0; j < 4; j++) {
                float4 xv = xr[j];
                ffma2(acc, q[2 * j],     make_float2(xv.x, xv.y));
                ffma2(acc, q[2 * j + 1], make_float2(xv.z, xv.w));
            }
            float p = acc.x + acc.y;
            p += __shfl_xor_sync(0xffffffffu, p, 16);   // fold dg pair
            if (lane < 16) red[wid][lane * 17 + n] = p;
        }
        __syncthreads();

        // fused dist-assembly + softmax: thread (rkk = tid&15, rn = tid>>4).
        {
            int rkk = tid & 15, rn = tid >> 4;
            float s = qkb_s[rkk];
#pragma unroll
            for (int w = 0; w < 8; w++) s += red[w][rkk * 17 + rn];
            float mx = s;
#pragma unroll
            for (int o = 1; o < 16; o <<= 1)
                mx = fmaxf(mx, __shfl_xor_sync(0xffffffffu, mx, o));
            float e = __expf(s - mx);
            float sm = e;
#pragma unroll
            for (int o = 1; o < 16; o <<= 1)
                sm += __shfl_xor_sync(0xffffffffu, sm, o);
            attn[rkk][rn] = e * (1.0f / sm);
        }
        __syncthreads();

        if (tid < 16) {
#pragma unroll
            for (int n = 0; n < 16; n++) Sa += attn[tid][n];
        }

        // phase2: float4 x loads (broadcast), packed u accumulation
#pragma unroll
        for (int n = 0; n < 16; n++) {
            float w = attn[kk][n];
            float2 w2 = make_float2(w, w);
            const float4* xr = &buf[n * 64 + dg * 4];
#pragma unroll
            for (int j = 0; j < 4; j++) {
                float4 xv = xr[j];
                ffma2(u[2 * j],     w2, make_float2(xv.x, xv.y));
                ffma2(u[2 * j + 1], w2, make_float2(xv.z, xv.w));
            }
        }
        __syncthreads();   // all reads of buf done -> safe to prefetch into it
    }

    float4* up = (float4*)(g_upart + (((size_t)ch * BB + b) * KS + kk) * DI + dg * 16);
    up[0] = make_float4(u[0].x, u[0].y, u[1].x, u[1].y);
    up[1] = make_float4(u[2].x, u[2].y, u[3].x, u[3].y);
    up[2] = make_float4(u[4].x, u[4].y, u[5].x, u[5].y);
    up[3] = make_float4(u[6].x, u[6].y, u[7].x, u[7].y);
    if (tid < 16) g_Spart[(ch * BB + b) * KS + tid] = Sa;
}

// ---------------- reduce partials, V proj + LN2 partial stats -----------
// grid: BB x 4; 4 slots per block; emits per-(b,kh) stat partials.
__global__ void __launch_bounds__(256) k_vproj(const float* __restrict__ vb, int t) {
    int b = blockIdx.x, kh = blockIdx.y, tid = threadIdx.x;
    int wid = tid >> 5, lane = tid & 31;
    __shared__ float wxs[4 * DI];
    __shared__ float wss[4], ivs[4];
    __shared__ float wsA[8], wsB[8];
    if (tid < 4) {
        float S = 0.f;
#pragma unroll 8
        for (int c = 0; c < NCH; c++) S += g_Spart[(c * BB + b) * KS + kh * 4 + tid];
        float iv = 1.0f / (S + 1e-7f);
        ivs[tid] = iv; wss[tid] = S * iv;
    }
    __syncthreads();
    {
        int k = tid >> 6, pos = tid & 63;   // 4 slots x 64 float4 = 256 threads
        const float4* src = (const float4*)g_upart +
            (((size_t)b * KS) + kh * 4 + k) * (DI / 4) + pos;
        float4 s = make_float4(0.f, 0.f, 0.f, 0.f);
#pragma unroll 8
        for (int c = 0; c < NCH; c++) {
            float4 v = src[(size_t)c * (BB * KS * DI / 4)];
            s.x += v.x; s.y += v.y; s.z += v.z; s.w += v.w;
        }
        float iv = ivs[k];
        s.x *= iv; s.y *= iv; s.z *= iv; s.w *= iv;
        ((float4*)wxs)[tid] = s;
    }
    __syncthreads();
    const float* vt = g_vWt + (size_t)t * DI * DO;
    float acc0 = 0.f, acc1 = 0.f, acc2 = 0.f, acc3 = 0.f;
#pragma unroll 8
    for (int d = 0; d < DI; d++) {
        float wv = vt[(size_t)d * DO + tid];
        acc0 += wxs[0 * DI + d] * wv;
        acc1 += wxs[1 * DI + d] * wv;
        acc2 += wxs[2 * DI + d] * wv;
        acc3 += wxs[3 * DI + d] * wv;
    }
    float vbv = vb[t * DO + tid];
    float v0 = acc0 + vbv * wss[0];
    float v1 = acc1 + vbv * wss[1];
    float v2 = acc2 + vbv * wss[2];
    float v3 = acc3 + vbv * wss[3];
    g_spre[b * KS * DO + (kh * 4 + 0) * DO + tid] = v0;
    g_spre[b * KS * DO + (kh * 4 + 1) * DO + tid] = v1;
    g_spre[b * KS * DO + (kh * 4 + 2) * DO + tid] = v2;
    g_spre[b * KS * DO + (kh * 4 + 3) * DO + tid] = v3;
    // partial LN2 stats over this block's 4 slots
    float s  = v0 + v1 + v2 + v3;
    float s2 = v0 * v0 + v1 * v1 + v2 * v2 + v3 * v3;
#pragma unroll
    for (int o = 16; o > 0; o >>= 1) {
        s  += __shfl_xor_sync(0xffffffffu, s,  o);
        s2 += __shfl_xor_sync(0xffffffffu, s2, o);
    }
    if (lane == 0) { wsA[wid] = s; wsB[wid] = s2; }
    __syncthreads();
    if (tid == 0) {
        float S = 0.f, S2 = 0.f;
#pragma unroll
        for (int j = 0; j < 8; j++) { S += wsA[j]; S2 += wsB[j]; }
        g_lnqA[b * 4 + kh] = S;
        g_lnqB[b * 4 + kh] = S2;
    }
}

// ---------------- LN2 + MLP + residual  (grid: 8 kq x 16 bg) ------------
// Batch-grouped: 2 slots x 4 batches; finalizes LN2 stats from k_vproj
// partials; emits LN1 stat partials for the NEXT iteration's k_qk.
__global__ void __launch_bounds__(256) k_mlp(const float* __restrict__ ln2w,
                                             const float* __restrict__ ln2b,
                                             const float* __restrict__ m1b,
                                             const float* __restrict__ m2b,
                                             int t, float* __restrict__ out) {
    int kq = blockIdx.x, bg = blockIdx.y, tid = threadIdx.x;
    int wid = tid >> 5, lane = tid & 31;
    int b0 = bg * 4, k0 = kq * 2;
    __shared__ float h0[8 * DO];    // 8 KB, row = bl*2 + k
    __shared__ float hh[8 * HI];    // 16 KB
    __shared__ float bm2[4], br2[4];
    __shared__ float wsA[4][8], wsB[4][8];
    if (tid < 4) {
        int b = b0 + tid;
        float s = 0.f, s2 = 0.f;
#pragma unroll
        for (int j = 0; j < 4; j++) { s += g_lnqA[b * 4 + j]; s2 += g_lnqB[b * 4 + j]; }
        const float inv = 1.0f / (float)(KS * DO);
        float m = s * inv;
        bm2[tid] = m;
        br2[tid] = rsqrtf(s2 * inv - m * m + LN_EPS);
    }
    __syncthreads();
    for (int idx = tid; idx < 8 * DO; idx += 256) {
        int row = idx >> 8, d = idx & 255;
        int bl = row >> 1, b = b0 + bl, sl = k0 + (row & 1);
        float v = g_spre[(size_t)b * KS * DO + sl * DO + d];
        h0[idx] = (v - bm2[bl]) * br2[bl] * ln2w[sl * DO + d] + ln2b[sl * DO + d];
    }
    __syncthreads();

    const float* w1 = g_m1Wt + (size_t)t * DO * HI;
    float2 a0[4], a1[4];
#pragma unroll
    for (int p = 0; p < 4; p++) { a0[p] = make_float2(0.f, 0.f); a1[p] = make_float2(0.f, 0.f); }
#pragma unroll 8
    for (int d = 0; d < DO; d++) {
        float wA = w1[(size_t)d * HI + tid];
        float wB = w1[(size_t)d * HI + tid + 256];
        float2 wa = make_float2(wA, wA), wb2 = make_float2(wB, wB);
#pragma unroll
        for (int p = 0; p < 4; p++) {
            float2 hp = make_float2(h0[(2 * p) * DO + d], h0[(2 * p + 1) * DO + d]);
            ffma2(a0[p], hp, wa);
            ffma2(a1[p], hp, wb2);
        }
    }
    float bA = m1b[t * HI + tid], bB = m1b[t * HI + tid + 256];
#pragma unroll
    for (int p = 0; p < 4; p++) {
        hh[(2 * p) * HI + tid]           = fmaxf(a0[p].x + bA, 0.f);
        hh[(2 * p + 1) * HI + tid]       = fmaxf(a0[p].y + bA, 0.f);
        hh[(2 * p) * HI + tid + 256]     = fmaxf(a1[p].x + bB, 0.f);
        hh[(2 * p + 1) * HI + tid + 256] = fmaxf(a1[p].y + bB, 0.f);
    }
    __syncthreads();

    const float* w2 = g_m2Wt + (size_t)t * HI * DO;
    float2 a2[4];
#pragma unroll
    for (int p = 0; p < 4; p++) a2[p] = make_float2(0.f, 0.f);
#pragma unroll 8
    for (int h = 0; h < HI; h++) {
        float wv = w2[(size_t)h * DO + tid];
        float2 w2v = make_float2(wv, wv);
#pragma unroll
        for (int p = 0; p < 4; p++)
            ffma2(a2[p], make_float2(hh[(2 * p) * HI + h], hh[(2 * p + 1) * HI + h]), w2v);
    }
    float b2 = m2b[t * DO + tid];
    float v0a[4], v1a[4];
#pragma unroll
    for (int p = 0; p < 4; p++) {
        int b = b0 + p;
        size_t gi0 = (size_t)b * KS * DO + (k0 + 0) * DO + tid;
        size_t gi1 = (size_t)b * KS * DO + (k0 + 1) * DO + tid;
        float v0 = g_spre[gi0] + a2[p].x + b2;
        float v1 = g_spre[gi1] + a2[p].y + b2;
        v0a[p] = v0; v1a[p] = v1;
        g_slots[gi0] = v0;
        g_slots[gi1] = v1;
        if (out) { out[gi0] = v0; out[gi1] = v1; }
    }
    // partial LN1 stats (over this block's 2 slots) for next iteration
#pragma unroll
    for (int p = 0; p < 4; p++) {
        float s  = v0a[p] + v1a[p];
        float s2 = v0a[p] * v0a[p] + v1a[p] * v1a[p];
#pragma unroll
        for (int o = 16; o > 0; o >>= 1) {
            s  += __shfl_xor_sync(0xffffffffu, s,  o);
            s2 += __shfl_xor_sync(0xffffffffu, s2, o);
        }
        if (lane == 0) { wsA[p][wid] = s; wsB[p][wid] = s2; }
    }
    __syncthreads();
    if (tid < 4) {
        float s = 0.f, s2 = 0.f;
#pragma unroll
        for (int j = 0; j < 8; j++) { s += wsA[tid][j]; s2 += wsB[tid][j]; }
        g_lnpA[(b0 + tid) * 8 + kq] = s;
        g_lnpB[(b0 + tid) * 8 + kq] = s2;
    }
}

// ---------------- host launcher -----------------------------------------
extern "C" void kernel_launch(void* const* d_in, const int* in_sizes, int n_in,
                              void* d_out, int out_size) {
    const float* inputs     = (const float*)d_in[0];
    const float* slots_init = (const float*)d_in[1];
    const float* mu         = (const float*)d_in[2];
    const float* logsigma   = (const float*)d_in[3];
    const float* ln0w       = (const float*)d_in[4];
    const float* ln0b       = (const float*)d_in[5];
    const float* ln1w       = (const float*)d_in[6];
    const float* ln1b       = (const float*)d_in[7];
    const float* ln2w       = (const float*)d_in[8];
    const float* ln2b       = (const float*)d_in[9];
    const float* qW         = (const float*)d_in[10];
    const float* qb         = (const float*)d_in[11];
    const float* kW         = (const float*)d_in[12];
    const float* kb         = (const float*)d_in[13];
    const float* vW         = (const float*)d_in[14];
    const float* vb         = (const float*)d_in[15];
    const float* m1W        = (const float*)d_in[16];
    const float* m1b        = (const float*)d_in[17];
    const float* m2W        = (const float*)d_in[18];
    const float* m2b        = (const float*)d_in[19];
    float* out = (float*)d_out;

    float* vWt;  cudaGetSymbolAddress((void**)&vWt,  g_vWt);
    float* m1Wt; cudaGetSymbolAddress((void**)&m1Wt, g_m1Wt);
    float* m2Wt; cudaGetSymbolAddress((void**)&m2Wt, g_m2Wt);

    k_tr<<<dim3(DI / 32, DO / 32, TT), 256>>>(vW, vWt, DO, DI);
    k_tr<<<dim3(DO / 32, HI / 32, TT), 256>>>(m1W, m1Wt, HI, DO);
    k_tr<<<dim3(HI / 32, DO / 32, TT), 256>>>(m2W, m2Wt, DO, HI);

    k_wqk<<<dim3(64, TT), 256>>>(qW, qb, kW, kb);   // all iterations up front
    k_stats<<<dim3(BB, SCH), 256>>>(inputs);
    k_fin<<<1, BB>>>();
    k_ln0<<<dim3(BB, SCH), 256>>>(inputs, ln0w, ln0b);
    k_sinit<<<BB, 256>>>(slots_init, mu, logsigma);

    for (int t = 0; t < TT; t++) {
        k_qk<<<dim3(8, 8), 256>>>(ln1w, ln1b, t, t == 0 ? 1 : 0);
        k_attn<<<dim3(BB, NCH), 256>>>();
        k_vproj<<<dim3(BB, 4), 256>>>(vb, t);
        k_mlp<<<dim3(8, 16), 256>>>(ln2w, ln2b, m1b, m2b, t,
                                    (t == TT - 1) ? out : (float*)nullptr);
    }
}

// round 17
// speedup vs baseline: 1.0983x; 1.0788x over previous
#include <cuda_runtime.h>
#include <math.h>

#define BB 64
#define NN 4096
#define KS 16
#define DI 256
#define DO 256
#define HI 512
#define TT 3
#define LN_EPS 1e-5f
#define NCH 32   // n-chunks for the big attention pass (128 rows per block)
#define SCH 32   // chunks for streaming passes

// packed fp32x2 FMA (Blackwell FFMA2 — only reachable via PTX)
__device__ __forceinline__ void ffma2(float2& d, float2 a, float2 b) {
    asm("fma.rn.f32x2 %0, %1, %2, %0;"
        : "+l"(reinterpret_cast<unsigned long long&>(d))
        : "l"(reinterpret_cast<unsigned long long&>(a)),
          "l"(reinterpret_cast<unsigned long long&>(b)));
}

// cp.async helpers (LDGSTS)
__device__ __forceinline__ void cpasync16(void* smem, const void* gmem) {
    unsigned a = (unsigned)__cvta_generic_to_shared(smem);
    asm volatile("cp.async.cg.shared.global [%0], [%1], 16;" :: "r"(a), "l"(gmem));
}
__device__ __forceinline__ void cp_commit() {
    asm volatile("cp.async.commit_group;");
}
template <int N>
__device__ __forceinline__ void cp_wait() {
    asm volatile("cp.async.wait_group %0;" :: "n"(N));
}

// ---------------- device scratch (static, no allocations) ----------------
__device__ float g_spartA[SCH * BB];
__device__ float g_spartB[SCH * BB];
__device__ float g_mean[BB];
__device__ float g_rstd[BB];
__device__ float g_lnm[BB];        // LN1/LN2 stats (reused per stage)
__device__ float g_lnr[BB];
__device__ float g_xn[(size_t)BB * NN * DI];   // LN0(x), 268 MB
__device__ float g_slots[BB * KS * DO];
__device__ float g_qk[BB * KS * DI];     // PRE-scaled by 1/KS
__device__ float g_qkb[BB * KS];         // PRE-scaled by 1/KS
__device__ float g_upart[(size_t)NCH * BB * KS * DI];
__device__ float g_Spart[NCH * BB * KS];
__device__ float g_spre[BB * KS * DO];
// folded / transposed weights (per-iteration buffers, filled up front)
__device__ float g_Wqk[TT * DO * DI];
__device__ float g_wqb[TT * DI];
__device__ float g_wb[TT * DO];
__device__ float g_c0[TT];
__device__ float g_vWt[TT * DI * DO];
__device__ float g_m1Wt[TT * DO * HI];
__device__ float g_m2Wt[TT * HI * DO];

// ---------------- generic 32x32 tiled transpose -------------------------
__global__ void __launch_bounds__(256) k_tr(const float* __restrict__ src,
                                            float* __restrict__ dst, int R, int C) {
    __shared__ float tile[32][33];
    int z = blockIdx.z;
    const float* s = src + (size_t)z * R * C;
    float* d = dst + (size_t)z * R * C;
    int c0 = blockIdx.x * 32, r0 = blockIdx.y * 32;
    int x = threadIdx.x & 31, y = threadIdx.x >> 5;
    for (int yy = y; yy < 32; yy += 8)
        tile[yy][x] = s[(size_t)(r0 + yy) * C + c0 + x];
    __syncthreads();
    for (int yy = y; yy < 32; yy += 8)
        d[(size_t)(c0 + yy) * R + r0 + x] = tile[x][yy];
}

// ---------------- LN0 statistics ----------------------------------------
__global__ void __launch_bounds__(256) k_stats(const float* __restrict__ in) {
    int b = blockIdx.x, c = blockIdx.y, tid = threadIdx.x;
    const float4* p = (const float4*)(in + (size_t)b * NN * DI);
    const int per = (NN * DI / 4) / SCH;
    float s = 0.f, s2 = 0.f;
    for (int i = tid; i < per; i += 256) {
        float4 v = p[(size_t)c * per + i];
        s  += v.x + v.y + v.z + v.w;
        s2 += v.x * v.x + v.y * v.y + v.z * v.z + v.w * v.w;
    }
    __shared__ float r1[256], r2[256];
    r1[tid] = s; r2[tid] = s2; __syncthreads();
    for (int o = 128; o > 0; o >>= 1) {
        if (tid < o) { r1[tid] += r1[tid + o]; r2[tid] += r2[tid + o]; }
        __syncthreads();
    }
    if (tid == 0) { g_spartA[c * BB + b] = r1[0]; g_spartB[c * BB + b] = r2[0]; }
}

__global__ void k_fin() {
    int b = threadIdx.x;
    if (b >= BB) return;
    float s = 0.f, s2 = 0.f;
    for (int c = 0; c < SCH; c++) { s += g_spartA[c * BB + b]; s2 += g_spartB[c * BB + b]; }
    const float inv = 1.0f / (float)(NN * DI);
    float m = s * inv;
    float v = s2 * inv - m * m;
    g_mean[b] = m;
    g_rstd[b] = rsqrtf(v + LN_EPS);
}

// ---------------- x_hat = LN0(x) materialized once ----------------------
__global__ void __launch_bounds__(256) k_ln0(const float* __restrict__ in,
                                             const float* __restrict__ w,
                                             const float* __restrict__ bb) {
    int b = blockIdx.x, c = blockIdx.y, tid = threadIdx.x;
    const int per = (NN * DI / 4) / SCH;   // 8192 float4
    float mean = g_mean[b], rstd = g_rstd[b];
    const float4* xin = (const float4*)(in + (size_t)b * NN * DI) + (size_t)c * per;
    const float4* w4  = (const float4*)w  + (size_t)c * per;
    const float4* b4  = (const float4*)bb + (size_t)c * per;
    float4* xo = (float4*)(g_xn + (size_t)b * NN * DI) + (size_t)c * per;
    for (int i = tid; i < per; i += 256) {
        float4 v = xin[i], ww = w4[i], bv = b4[i], o;
        o.x = (v.x - mean) * rstd * ww.x + bv.x;
        o.y = (v.y - mean) * rstd * ww.y + bv.y;
        o.z = (v.z - mean) * rstd * ww.z + bv.z;
        o.w = (v.w - mean) * rstd * ww.w + bv.w;
        xo[i] = o;
    }
}

// ---------------- slots = mu + exp(logsigma) * slots_init ---------------
__global__ void k_sinit(const float* __restrict__ si, const float* __restrict__ mu,
                        const float* __restrict__ ls) {
    int i = blockIdx.x * 256 + threadIdx.x;
    int d = i & (DO - 1);
    g_slots[i] = mu[d] + expf(ls[d]) * si[i];
}

// ---------------- per-batch LN stats over [KS, DO]  (grid: BB) ----------
__global__ void __launch_bounds__(256) k_lnst(const float* __restrict__ src) {
    int b = blockIdx.x, tid = threadIdx.x;
    __shared__ float r1[256], r2[256];
    const float4* p = (const float4*)(src + (size_t)b * KS * DO);
    float s = 0.f, s2 = 0.f;
    for (int i = tid; i < KS * DO / 4; i += 256) {
        float4 v = p[i];
        s  += v.x + v.y + v.z + v.w;
        s2 += v.x * v.x + v.y * v.y + v.z * v.z + v.w * v.w;
    }
    r1[tid] = s; r2[tid] = s2; __syncthreads();
    for (int o = 128; o > 0; o >>= 1) {
        if (tid < o) { r1[tid] += r1[tid + o]; r2[tid] += r2[tid + o]; }
        __syncthreads();
    }
    if (tid == 0) {
        const float inv = 1.0f / (float)(KS * DO);
        float m = r1[0] * inv;
        g_lnm[b] = m;
        g_lnr[b] = rsqrtf(r2[0] * inv - m * m + LN_EPS);
    }
}

// ---------------- Wqk = qW^T @ kW  (grid: 64 x TT) ----------------------
__global__ void __launch_bounds__(256) k_wqk(const float* __restrict__ qW,
                                             const float* __restrict__ qb,
                                             const float* __restrict__ kW,
                                             const float* __restrict__ kb) {
    int d0 = blockIdx.x * 4, t = blockIdx.y, i = threadIdx.x;
    int wid = i >> 5, lane = i & 31;
    __shared__ float qcols[DO * 4];
    __shared__ float kb_s[DO], qb_s[DO];
    {
        float4 v = *(const float4*)(qW + (size_t)t * DO * DO + (size_t)i * DO + d0);
        qcols[i * 4 + 0] = v.x; qcols[i * 4 + 1] = v.y;
        qcols[i * 4 + 2] = v.z; qcols[i * 4 + 3] = v.w;
        kb_s[i] = kb[t * DO + i];
        qb_s[i] = qb[t * DO + i];
    }
    __syncthreads();
    const float* kWt = kW + (size_t)t * DO * DI;
    float acc0 = 0.f, acc1 = 0.f, acc2 = 0.f, acc3 = 0.f, accq = 0.f;
#pragma unroll 8
    for (int e = 0; e < DO; e++) {
        float kv = kWt[(size_t)e * DI + i];
        acc0 += qcols[e * 4 + 0] * kv;
        acc1 += qcols[e * 4 + 1] * kv;
        acc2 += qcols[e * 4 + 2] * kv;
        acc3 += qcols[e * 4 + 3] * kv;
        accq += qb_s[e] * kv;
    }
    float* Wq = g_Wqk + (size_t)t * DO * DI;
    Wq[(d0 + 0) * DI + i] = acc0;
    Wq[(d0 + 1) * DI + i] = acc1;
    Wq[(d0 + 2) * DI + i] = acc2;
    Wq[(d0 + 3) * DI + i] = acc3;
    if (blockIdx.x == 0) g_wqb[t * DI + i] = accq;
    if (wid < 4) {
        float s = 0.f;
        for (int e = lane; e < DO; e += 32) s += qcols[e * 4 + wid] * kb_s[e];
#pragma unroll
        for (int o = 16; o > 0; o >>= 1) s += __shfl_xor_sync(0xffffffffu, s, o);
        if (lane == 0) g_wb[t * DO + d0 + wid] = s;
    }
    if (blockIdx.x == 0 && wid == 4) {
        float s = 0.f;
        for (int e = lane; e < DO; e += 32) s += qb_s[e] * kb_s[e];
#pragma unroll
        for (int o = 16; o > 0; o >>= 1) s += __shfl_xor_sync(0xffffffffu, s, o);
        if (lane == 0) g_c0[t] = s;
    }
}

// ---------------- LN1(slots) -> qk = sn @ Wqk + wqb  (grid: BB x 8) -----
// 2 slots per block (512 blocks: better latency hiding for the dot loops)
__global__ void __launch_bounds__(256) k_qk(const float* __restrict__ ln1w,
                                            const float* __restrict__ ln1b, int t) {
    int b = blockIdx.x, kh = blockIdx.y, tid = threadIdx.x;
    int wid = tid >> 5, lane = tid & 31;
    __shared__ float ss[2 * DO];
    float m = g_lnm[b], rs = g_lnr[b];
    for (int i = tid; i < 2 * DO; i += 256) {
        int gi = kh * 2 * DO + i;
        float v = g_slots[b * KS * DO + gi];
        ss[i] = (v - m) * rs * ln1w[gi] + ln1b[gi];
    }
    __syncthreads();

    const float isc = 1.0f / (float)KS;
    const float* Wq = g_Wqk + (size_t)t * DO * DI;
    float acc0 = 0.f, acc1 = 0.f;
#pragma unroll 16
    for (int d = 0; d < DO; d++) {
        float wv = Wq[d * DI + tid];
        acc0 += ss[d] * wv;
        acc1 += ss[DO + d] * wv;
    }
    float wqbv = g_wqb[t * DI + tid];
    g_qk[b * KS * DI + (kh * 2 + 0) * DI + tid] = (acc0 + wqbv) * isc;
    g_qk[b * KS * DI + (kh * 2 + 1) * DI + tid] = (acc1 + wqbv) * isc;
    if (wid < 2) {
        float sb = 0.f;
        const float* wb = g_wb + t * DO;
        for (int d = lane; d < DO; d += 32) sb += ss[wid * DO + d] * wb[d];
#pragma unroll
        for (int o = 16; o > 0; o >>= 1) sb += __shfl_xor_sync(0xffffffffu, sb, o);
        if (lane == 0) g_qkb[b * KS + kh * 2 + wid] = (sb + g_c0[t]) * isc;
    }
}

// ---------------- big fused attention pass  (grid: BB x NCH) ------------
// 3-barrier pipelined tile loop: end-of-tile barrier removed; prefetch for
// tile g+1 issued after barrier [1] of tile g, which already orders all of
// tile g-1's reads of the destination buffer. occ 3 (regs=80).
__global__ void __launch_bounds__(256, 3) k_attn() {
    int b = blockIdx.x, ch = blockIdx.y, tid = threadIdx.x;
    int kk = tid & 15, dg = tid >> 4;
    int wid = tid >> 5, lane = tid & 31;

    __shared__ float4 xs[2][16 * 64];    // double-buffered tiles, 32 KB
    __shared__ float  attn[KS][17];
    __shared__ float  red[8][16 * 17];
    __shared__ float  qkb_s[KS];

    // qk segment for (kk, dg): 16 floats as 8 float2 (already /KS scaled)
    const float2* qp = (const float2*)(g_qk + ((size_t)b * KS + kk) * DI + dg * 16);
    float2 q[8];
#pragma unroll
    for (int j = 0; j < 8; j++) q[j] = qp[j];
    if (tid < KS) qkb_s[tid] = g_qkb[b * KS + tid];

    float2 u[8];
#pragma unroll
    for (int j = 0; j < 8; j++) u[j] = make_float2(0.f, 0.f);
    float Sa = 0.f;

    const float4* xnb = (const float4*)(g_xn + ((size_t)b * NN + (size_t)ch * 128) * DI);

    // prefetch tile 0 (linear layout, stride 64 float4)
#pragma unroll
    for (int k = 0; k < 4; k++) {
        int i = tid + k * 256;
        cpasync16(&xs[0][i], &xnb[i]);
    }
    cp_commit();

    for (int g = 0; g < 8; g++) {
        const float4* buf = xs[g & 1];
        cp_wait<0>();
        __syncthreads();   // [1] tile g visible; g-1's reads of other buffer done

        // issue prefetch for tile g+1 (overlaps phase1/softmax/phase2)
        if (g < 7) {
            float4* nb = xs[(g + 1) & 1];
            const float4* src = xnb + (size_t)(g + 1) * 1024;
#pragma unroll
            for (int k = 0; k < 4; k++) {
                int i = tid + k * 256;
                cpasync16(&nb[i], &src[i]);
            }
            cp_commit();
        }

        // phase1: float4 partial dots; immediate shfl-fold + store
#pragma unroll
        for (int n = 0; n < 16; n++) {
            const float4* xr = &buf[n * 64 + dg * 4];
            float2 acc = make_float2(0.f, 0.f);
#pragma unroll
            for (int j = 0; j < 4; j++) {
                float4 xv = xr[j];
                ffma2(acc, q[2 * j],     make_float2(xv.x, xv.y));
                ffma2(acc, q[2 * j + 1], make_float2(xv.z, xv.w));
            }
            float p = acc.x + acc.y;
            p += __shfl_xor_sync(0xffffffffu, p, 16);   // fold dg pair
            if (lane < 16) red[wid][lane * 17 + n] = p;
        }
        __syncthreads();   // [2]

        // fused dist-assembly + softmax: thread (rkk = tid&15, rn = tid>>4).
        {
            int rkk = tid & 15, rn = tid >> 4;
            float s = qkb_s[rkk];
#pragma unroll
            for (int w = 0; w < 8; w++) s += red[w][rkk * 17 + rn];
            float mx = s;
#pragma unroll
            for (int o = 1; o < 16; o <<= 1)
                mx = fmaxf(mx, __shfl_xor_sync(0xffffffffu, mx, o));
            float e = __expf(s - mx);
            float sm = e;
#pragma unroll
            for (int o = 1; o < 16; o <<= 1)
                sm += __shfl_xor_sync(0xffffffffu, sm, o);
            attn[rkk][rn] = e * (1.0f / sm);
        }
        __syncthreads();   // [3]

        if (tid < 16) {
#pragma unroll
            for (int n = 0; n < 16; n++) Sa += attn[tid][n];
        }

        // phase2: float4 x loads (broadcast), packed u accumulation
#pragma unroll
        for (int n = 0; n < 16; n++) {
            float w = attn[kk][n];
            float2 w2 = make_float2(w, w);
            const float4* xr = &buf[n * 64 + dg * 4];
#pragma unroll
            for (int j = 0; j < 4; j++) {
                float4 xv = xr[j];
                ffma2(u[2 * j],     w2, make_float2(xv.x, xv.y));
                ffma2(u[2 * j + 1], w2, make_float2(xv.z, xv.w));
            }
        }
        // no trailing barrier: next iteration's [1] provides the ordering
    }

    float4* up = (float4*)(g_upart + (((size_t)ch * BB + b) * KS + kk) * DI + dg * 16);
    up[0] = make_float4(u[0].x, u[0].y, u[1].x, u[1].y);
    up[1] = make_float4(u[2].x, u[2].y, u[3].x, u[3].y);
    up[2] = make_float4(u[4].x, u[4].y, u[5].x, u[5].y);
    up[3] = make_float4(u[6].x, u[6].y, u[7].x, u[7].y);
    if (tid < 16) g_Spart[(ch * BB + b) * KS + tid] = Sa;
}

// ---------------- reduce partials, V proj  (grid: BB x 4) ---------------
// 4 slots per block; one thread per (slot, float4-pos) in the reduce.
__global__ void __launch_bounds__(256) k_vproj(const float* __restrict__ vb, int t) {
    int b = blockIdx.x, kh = blockIdx.y, tid = threadIdx.x;
    __shared__ float wxs[4 * DI];
    __shared__ float wss[4], ivs[4];
    if (tid < 4) {
        float S = 0.f;
#pragma unroll 8
        for (int c = 0; c < NCH; c++) S += g_Spart[(c * BB + b) * KS + kh * 4 + tid];
        float iv = 1.0f / (S + 1e-7f);
        ivs[tid] = iv; wss[tid] = S * iv;
    }
    __syncthreads();
    {
        int k = tid >> 6, pos = tid & 63;   // 4 slots x 64 float4 = 256 threads
        const float4* src = (const float4*)g_upart +
            (((size_t)b * KS) + kh * 4 + k) * (DI / 4) + pos;
        float4 s = make_float4(0.f, 0.f, 0.f, 0.f);
#pragma unroll 8
        for (int c = 0; c < NCH; c++) {
            float4 v = src[(size_t)c * (BB * KS * DI / 4)];
            s.x += v.x; s.y += v.y; s.z += v.z; s.w += v.w;
        }
        float iv = ivs[k];
        s.x *= iv; s.y *= iv; s.z *= iv; s.w *= iv;
        ((float4*)wxs)[tid] = s;
    }
    __syncthreads();
    const float* vt = g_vWt + (size_t)t * DI * DO;
    float acc0 = 0.f, acc1 = 0.f, acc2 = 0.f, acc3 = 0.f;
#pragma unroll 8
    for (int d = 0; d < DI; d++) {
        float wv = vt[(size_t)d * DO + tid];
        acc0 += wxs[0 * DI + d] * wv;
        acc1 += wxs[1 * DI + d] * wv;
        acc2 += wxs[2 * DI + d] * wv;
        acc3 += wxs[3 * DI + d] * wv;
    }
    float vbv = vb[t * DO + tid];
    g_spre[b * KS * DO + (kh * 4 + 0) * DO + tid] = acc0 + vbv * wss[0];
    g_spre[b * KS * DO + (kh * 4 + 1) * DO + tid] = acc1 + vbv * wss[1];
    g_spre[b * KS * DO + (kh * 4 + 2) * DO + tid] = acc2 + vbv * wss[2];
    g_spre[b * KS * DO + (kh * 4 + 3) * DO + tid] = acc3 + vbv * wss[3];
}

// ---------------- LN2 + MLP + residual  (grid: BB x 8, 2 slots) ---------
__global__ void __launch_bounds__(256) k_mlp(const float* __restrict__ ln2w,
                                             const float* __restrict__ ln2b,
                                             const float* __restrict__ m1b,
                                             const float* __restrict__ m2b,
                                             int t, float* __restrict__ out) {
    int b = blockIdx.x, kq = blockIdx.y, tid = threadIdx.x;
    __shared__ float h0[2 * DO];
    __shared__ float hh[2 * HI];
    float m = g_lnm[b], rs = g_lnr[b];
    for (int i = tid; i < 2 * DO; i += 256) {
        int gi = kq * 2 * DO + i;
        float v = g_spre[b * KS * DO + gi];
        h0[i] = (v - m) * rs * ln2w[gi] + ln2b[gi];
    }
    __syncthreads();

    const float* w1 = g_m1Wt + (size_t)t * DO * HI;
    {
        float a00 = 0.f, a01 = 0.f, a10 = 0.f, a11 = 0.f;
#pragma unroll 8
        for (int d = 0; d < DO; d++) {
            float wA = w1[(size_t)d * HI + tid];
            float wB = w1[(size_t)d * HI + tid + 256];
            float h0v = h0[d], h1v = h0[DO + d];
            a00 += h0v * wA; a01 += h0v * wB;
            a10 += h1v * wA; a11 += h1v * wB;
        }
        float bA = m1b[t * HI + tid], bB = m1b[t * HI + tid + 256];
        hh[0 * HI + tid]       = fmaxf(a00 + bA, 0.f);
        hh[0 * HI + tid + 256] = fmaxf(a01 + bB, 0.f);
        hh[1 * HI + tid]       = fmaxf(a10 + bA, 0.f);
        hh[1 * HI + tid + 256] = fmaxf(a11 + bB, 0.f);
    }
    __syncthreads();

    const float* w2 = g_m2Wt + (size_t)t * HI * DO;
    float a0 = 0.f, a1 = 0.f;
#pragma unroll 8
    for (int h = 0; h < HI; h++) {
        float wv = w2[(size_t)h * DO + tid];
        a0 += hh[h] * wv;
        a1 += hh[HI + h] * wv;
    }
    float b2 = m2b[t * DO + tid];
    {
        int gi0 = (kq * 2 + 0) * DO + tid;
        int gi1 = (kq * 2 + 1) * DO + tid;
        float v0 = g_spre[b * KS * DO + gi0] + a0 + b2;
        float v1 = g_spre[b * KS * DO + gi1] + a1 + b2;
        g_slots[b * KS * DO + gi0] = v0;
        g_slots[b * KS * DO + gi1] = v1;
        if (out) {
            out[(size_t)b * KS * DO + gi0] = v0;
            out[(size_t)b * KS * DO + gi1] = v1;
        }
    }
}

// ---------------- host launcher -----------------------------------------
extern "C" void kernel_launch(void* const* d_in, const int* in_sizes, int n_in,
                              void* d_out, int out_size) {
    const float* inputs     = (const float*)d_in[0];
    const float* slots_init = (const float*)d_in[1];
    const float* mu         = (const float*)d_in[2];
    const float* logsigma   = (const float*)d_in[3];
    const float* ln0w       = (const float*)d_in[4];
    const float* ln0b       = (const float*)d_in[5];
    const float* ln1w       = (const float*)d_in[6];
    const float* ln1b       = (const float*)d_in[7];
    const float* ln2w       = (const float*)d_in[8];
    const float* ln2b       = (const float*)d_in[9];
    const float* qW         = (const float*)d_in[10];
    const float* qb         = (const float*)d_in[11];
    const float* kW         = (const float*)d_in[12];
    const float* kb         = (const float*)d_in[13];
    const float* vW         = (const float*)d_in[14];
    const float* vb         = (const float*)d_in[15];
    const float* m1W        = (const float*)d_in[16];
    const float* m1b        = (const float*)d_in[17];
    const float* m2W        = (const float*)d_in[18];
    const float* m2b        = (const float*)d_in[19];
    float* out = (float*)d_out;

    float* vWt;    cudaGetSymbolAddress((void**)&vWt,    g_vWt);
    float* m1Wt;   cudaGetSymbolAddress((void**)&m1Wt,   g_m1Wt);
    float* m2Wt;   cudaGetSymbolAddress((void**)&m2Wt,   g_m2Wt);
    float* slotsp; cudaGetSymbolAddress((void**)&slotsp, g_slots);
    float* sprep;  cudaGetSymbolAddress((void**)&sprep,  g_spre);

    k_tr<<<dim3(DI / 32, DO / 32, TT), 256>>>(vW, vWt, DO, DI);
    k_tr<<<dim3(DO / 32, HI / 32, TT), 256>>>(m1W, m1Wt, HI, DO);
    k_tr<<<dim3(HI / 32, DO / 32, TT), 256>>>(m2W, m2Wt, DO, HI);

    k_wqk<<<dim3(64, TT), 256>>>(qW, qb, kW, kb);   // all iterations up front
    k_stats<<<dim3(BB, SCH), 256>>>(inputs);
    k_fin<<<1, BB>>>();
    k_ln0<<<dim3(BB, SCH), 256>>>(inputs, ln0w, ln0b);
    k_sinit<<<(BB * KS * DO) / 256, 256>>>(slots_init, mu, logsigma);

    for (int t = 0; t < TT; t++) {
        k_lnst<<<BB, 256>>>(slotsp);
        k_qk<<<dim3(BB, 8), 256>>>(ln1w, ln1b, t);
        k_attn<<<dim3(BB, NCH), 256>>>();
        k_vproj<<<dim3(BB, 4), 256>>>(vb, t);
        k_lnst<<<BB, 256>>>(sprep);
        k_mlp<<<dim3(BB, 8), 256>>>(ln2w, ln2b, m1b, m2b, t,
                                    (t == TT - 1) ? out : (float*)nullptr);
    }
}